// round 1
// baseline (speedup 1.0000x reference)
#include <cuda_runtime.h>

// Problem constants
#define B_DIM 4
#define T_DIM 4096
#define C_DIM 384
#define H_DIM 64
#define BT_TOTAL (B_DIM * T_DIM)   // 16384

// Scratch for projected K and V (q == v per the reference's bug)
__device__ float g_K[BT_TOTAL * H_DIM];
__device__ float g_V[BT_TOTAL * H_DIM];

// ---------------------------------------------------------------------------
// Kernel 1: fused K/V projection.
//   g_K[r][h] = x[r] . Wk[h] + bk[h]
//   g_V[r][h] = x[r] . Wv[h] + bv[h]
// Treated as one GEMM: (16384 x 384) @ (384 x 128) with 128 features
// (f<64 -> K feature f, f>=64 -> V feature f-64).
// Block: 256 threads, tile 64 rows x 128 features, TK=32.
// ---------------------------------------------------------------------------
__global__ __launch_bounds__(256) void proj_kernel(
    const float* __restrict__ x,
    const float* __restrict__ Wk, const float* __restrict__ bk,
    const float* __restrict__ Wv, const float* __restrict__ bv)
{
    __shared__ float Xs[32][68];    // [kk][t], padded (16B-aligned rows)
    __shared__ float Ws[32][132];   // [kk][f], padded

    const int tid  = threadIdx.x;
    const int row0 = blockIdx.x * 64;
    const int kk_l = tid & 31;      // c within tile
    const int grp  = tid >> 5;      // 0..7

    const int ty = tid >> 4;        // 0..15 -> 4 rows each
    const int tx = tid & 15;        // 0..15 -> 8 features each

    float acc[4][8];
#pragma unroll
    for (int i = 0; i < 4; i++)
#pragma unroll
        for (int j = 0; j < 8; j++) acc[i][j] = 0.f;

    for (int c0 = 0; c0 < C_DIM; c0 += 32) {
        // Load X tile (coalesced on c), store transposed [kk][t]
#pragma unroll
        for (int tt = grp; tt < 64; tt += 8)
            Xs[kk_l][tt] = x[(size_t)(row0 + tt) * C_DIM + c0 + kk_l];
        // Load W tile (coalesced on c), [kk][f]
#pragma unroll
        for (int f = grp; f < 128; f += 8) {
            const float* Wrow = (f < 64) ? (Wk + (size_t)f * C_DIM)
                                         : (Wv + (size_t)(f - 64) * C_DIM);
            Ws[kk_l][f] = Wrow[c0 + kk_l];
        }
        __syncthreads();

#pragma unroll
        for (int kk = 0; kk < 32; kk++) {
            float4 a4 = *(const float4*)&Xs[kk][ty * 4];
            float4 b0 = *(const float4*)&Ws[kk][tx * 8];
            float4 b1 = *(const float4*)&Ws[kk][tx * 8 + 4];
            float a[4] = {a4.x, a4.y, a4.z, a4.w};
            float b[8] = {b0.x, b0.y, b0.z, b0.w, b1.x, b1.y, b1.z, b1.w};
#pragma unroll
            for (int i = 0; i < 4; i++)
#pragma unroll
                for (int j = 0; j < 8; j++)
                    acc[i][j] += a[i] * b[j];
        }
        __syncthreads();
    }

    // Epilogue: add bias, scatter to g_K / g_V
#pragma unroll
    for (int i = 0; i < 4; i++) {
        const int row = row0 + ty * 4 + i;
#pragma unroll
        for (int j = 0; j < 8; j++) {
            const int f = tx * 8 + j;
            if (f < 64) g_K[(size_t)row * H_DIM + f]        = acc[i][j] + bk[f];
            else        g_V[(size_t)row * H_DIM + (f - 64)] = acc[i][j] + bv[f - 64];
        }
    }
}

// ---------------------------------------------------------------------------
// Kernel 2: causal flash attention, fp32.
//   q == v (reference bug). scale = 1/sqrt(C_DIM).
// Block: 128 threads. BM=32 queries per CTA, 4 threads per query.
// Each sub-thread owns 4 interleaved float4 chunks (chunk = 4*i + sub) of the
// 64-dim head -> conflict-free LDS.128 from K/V tiles.
// KV tile BN=64 in shared. Online softmax, two-pass per tile with scores
// staged in shared (column-swizzled to kill bank conflicts without padding).
// ---------------------------------------------------------------------------
#define BM 32
#define BN 64

__global__ __launch_bounds__(128) void flash_kernel(float* __restrict__ out)
{
    __shared__ float Ks[BN][H_DIM];   // 16 KB
    __shared__ float Vs[BN][H_DIM];   // 16 KB
    __shared__ float Ss[BM][BN];      // 8 KB, swizzled columns

    const int tid  = threadIdx.x;
    const int warp = tid >> 5;
    const int lane = tid & 31;

    const int b  = blockIdx.y;
    const int qt = (int)gridDim.x - 1 - (int)blockIdx.x;  // longest tiles first

    const int q_local = warp * 8 + (lane >> 2);  // 0..31
    const int sub     = lane & 3;                // 0..3
    const int qi      = qt * BM + q_local;       // global query row

    const float* Kb = g_K + (size_t)b * T_DIM * H_DIM;
    const float* Vb = g_V + (size_t)b * T_DIM * H_DIM;

    // Load this thread's slice of q (= V row qi): chunks 4*i + sub
    float4 q4[4];
    {
        const float4* qp = (const float4*)(Vb + (size_t)qi * H_DIM);
#pragma unroll
        for (int i = 0; i < 4; i++) q4[i] = qp[4 * i + sub];
    }

    float acc[16];
#pragma unroll
    for (int i = 0; i < 16; i++) acc[i] = 0.f;
    float m = -1e30f, l = 0.f;
    const float scale = 0.05103103630798288f;  // 1/sqrt(384)

    const int kt_last = (qt * BM + (BM - 1)) >> 6;  // last KV tile index

    for (int kt = 0; kt <= kt_last; kt++) {
        // Cooperative load of K,V tiles (64x64 floats each = 1024 float4)
        {
            const float4* ksrc = (const float4*)(Kb + (size_t)kt * BN * H_DIM);
            const float4* vsrc = (const float4*)(Vb + (size_t)kt * BN * H_DIM);
            float4* kdst = (float4*)&Ks[0][0];
            float4* vdst = (float4*)&Vs[0][0];
#pragma unroll
            for (int i = 0; i < 8; i++) {
                kdst[tid + i * 128] = ksrc[tid + i * 128];
                vdst[tid + i * 128] = vsrc[tid + i * 128];
            }
        }
        __syncthreads();

        // Pass 1: scores for this query row
        const int rem  = qi - kt * BN + 1;            // #valid keys in tile
        const int jmax = rem > BN ? BN : rem;         // may be <= 0 (all masked)
        float tmax = -1e30f;
        for (int j = 0; j < BN; j++) {
            const float4* kr = (const float4*)&Ks[j][0];
            float s0 = 0.f, s1 = 0.f, s2 = 0.f, s3 = 0.f;
#pragma unroll
            for (int i = 0; i < 4; i++) {
                float4 kv = kr[4 * i + sub];
                s0 += q4[i].x * kv.x;
                s1 += q4[i].y * kv.y;
                s2 += q4[i].z * kv.z;
                s3 += q4[i].w * kv.w;
            }
            float s = (s0 + s1) + (s2 + s3);
            s += __shfl_xor_sync(0xffffffffu, s, 1);
            s += __shfl_xor_sync(0xffffffffu, s, 2);
            s *= scale;
            if (j >= jmax) s = -1e30f;               // causal mask
            if (sub == 0) Ss[q_local][(j + q_local) & (BN - 1)] = s;
            tmax = fmaxf(tmax, s);
        }
        __syncwarp();

        // Online softmax rescale
        const float mnew = fmaxf(m, tmax);
        const float corr = __expf(m - mnew);
        l *= corr;
#pragma unroll
        for (int d = 0; d < 16; d++) acc[d] *= corr;
        m = mnew;

        // Pass 2: p = exp(s - m), accumulate P*V
        for (int j = 0; j < BN; j++) {
            const float p = __expf(Ss[q_local][(j + q_local) & (BN - 1)] - mnew);
            l += p;
            const float4* vr = (const float4*)&Vs[j][0];
#pragma unroll
            for (int i = 0; i < 4; i++) {
                float4 vv = vr[4 * i + sub];
                acc[4 * i + 0] += p * vv.x;
                acc[4 * i + 1] += p * vv.y;
                acc[4 * i + 2] += p * vv.z;
                acc[4 * i + 3] += p * vv.w;
            }
        }
        __syncthreads();
    }

    // Epilogue: normalize and store
    const float inv_l = 1.f / l;
    float4* op = (float4*)(out + ((size_t)b * T_DIM + qi) * H_DIM);
#pragma unroll
    for (int i = 0; i < 4; i++) {
        float4 o;
        o.x = acc[4 * i + 0] * inv_l;
        o.y = acc[4 * i + 1] * inv_l;
        o.z = acc[4 * i + 2] * inv_l;
        o.w = acc[4 * i + 3] * inv_l;
        op[4 * i + sub] = o;
    }
}

// ---------------------------------------------------------------------------
// Launch. Inputs (metadata order): x, Wk, bk, Wq, bq, Wv, bv.
// Wq/bq are intentionally unused (reference uses the value projection for q).
// ---------------------------------------------------------------------------
extern "C" void kernel_launch(void* const* d_in, const int* in_sizes, int n_in,
                              void* d_out, int out_size)
{
    (void)in_sizes; (void)n_in; (void)out_size;
    const float* x  = (const float*)d_in[0];
    const float* Wk = (const float*)d_in[1];
    const float* bk = (const float*)d_in[2];
    const float* Wv = (const float*)d_in[5];
    const float* bv = (const float*)d_in[6];
    float* out = (float*)d_out;

    proj_kernel<<<BT_TOTAL / 64, 256>>>(x, Wk, bk, Wv, bv);

    dim3 grid(T_DIM / BM, B_DIM);
    flash_kernel<<<grid, 128>>>(out);
}

// round 2
// speedup vs baseline: 1.6179x; 1.6179x over previous
#include <cuda_runtime.h>

// Problem constants
#define B_DIM 4
#define T_DIM 4096
#define C_DIM 384
#define H_DIM 64
#define BT_TOTAL (B_DIM * T_DIM)   // 16384

// Scratch for projected K and V (q == v per the reference's bug)
__device__ float g_K[BT_TOTAL * H_DIM];
__device__ float g_V[BT_TOTAL * H_DIM];

// ---------------------------------------------------------------------------
// Kernel 1: fused K/V projection (unchanged from R1 — ~85us, revisit later).
// ---------------------------------------------------------------------------
__global__ __launch_bounds__(256) void proj_kernel(
    const float* __restrict__ x,
    const float* __restrict__ Wk, const float* __restrict__ bk,
    const float* __restrict__ Wv, const float* __restrict__ bv)
{
    __shared__ float Xs[32][68];
    __shared__ float Ws[32][132];

    const int tid  = threadIdx.x;
    const int row0 = blockIdx.x * 64;
    const int kk_l = tid & 31;
    const int grp  = tid >> 5;

    const int ty = tid >> 4;
    const int tx = tid & 15;

    float acc[4][8];
#pragma unroll
    for (int i = 0; i < 4; i++)
#pragma unroll
        for (int j = 0; j < 8; j++) acc[i][j] = 0.f;

    for (int c0 = 0; c0 < C_DIM; c0 += 32) {
#pragma unroll
        for (int tt = grp; tt < 64; tt += 8)
            Xs[kk_l][tt] = x[(size_t)(row0 + tt) * C_DIM + c0 + kk_l];
#pragma unroll
        for (int f = grp; f < 128; f += 8) {
            const float* Wrow = (f < 64) ? (Wk + (size_t)f * C_DIM)
                                         : (Wv + (size_t)(f - 64) * C_DIM);
            Ws[kk_l][f] = Wrow[c0 + kk_l];
        }
        __syncthreads();

#pragma unroll
        for (int kk = 0; kk < 32; kk++) {
            float4 a4 = *(const float4*)&Xs[kk][ty * 4];
            float4 b0 = *(const float4*)&Ws[kk][tx * 8];
            float4 b1 = *(const float4*)&Ws[kk][tx * 8 + 4];
            float a[4] = {a4.x, a4.y, a4.z, a4.w};
            float b[8] = {b0.x, b0.y, b0.z, b0.w, b1.x, b1.y, b1.z, b1.w};
#pragma unroll
            for (int i = 0; i < 4; i++)
#pragma unroll
                for (int j = 0; j < 8; j++)
                    acc[i][j] += a[i] * b[j];
        }
        __syncthreads();
    }

#pragma unroll
    for (int i = 0; i < 4; i++) {
        const int row = row0 + ty * 4 + i;
#pragma unroll
        for (int j = 0; j < 8; j++) {
            const int f = tx * 8 + j;
            if (f < 64) g_K[(size_t)row * H_DIM + f]        = acc[i][j] + bk[f];
            else        g_V[(size_t)row * H_DIM + (f - 64)] = acc[i][j] + bv[f - 64];
        }
    }
}

// ---------------------------------------------------------------------------
// Kernel 2: causal flash attention, fp32, 2D register-tiled.
//   q == v (reference bug). scale folded into Q at load.
// Block: 128 threads = 8(ty) x 16(tx). BM=BN=64.
// Thread microtiles: S = 8m x 4n (n = tx + 16j, strided for bank-free K reads)
//                    O = 8m x 4h (h = 4*tx, contiguous for bank-free V reads)
// P redistributed via shared roundtrip between the two GEMMs.
// Shared strides chosen so every hot LDS.128 is conflict-free:
//   Ks stride 76: n-strided mapping -> 8-lane phase covers all 32 banks.
//   Qs/Ps reads are phase-uniform broadcasts; Vs reads use h=4*tx.
// ---------------------------------------------------------------------------
#define SQ 68
#define SK 76
#define SV 68
#define SP 68
#define FLASH_SMEM (64 * (SQ + SK + SV + SP) * 4)   // 71680 bytes

__global__ __launch_bounds__(128) void flash_kernel(float* __restrict__ out)
{
    extern __shared__ float sm[];
    float* Qs = sm;                 // [64][SQ]
    float* Ks = Qs + 64 * SQ;       // [64][SK]
    float* Vs = Ks + 64 * SK;       // [64][SV]
    float* Ps = Vs + 64 * SV;       // [64][SP]

    const int tid = threadIdx.x;
    const int tx  = tid & 15;
    const int ty  = tid >> 4;

    const int b  = blockIdx.y;
    const int qt = (int)gridDim.x - 1 - (int)blockIdx.x;  // longest first

    const float* Kb = g_K + (size_t)b * T_DIM * H_DIM;
    const float* Vb = g_V + (size_t)b * T_DIM * H_DIM;

    const float scale = 0.05103103630798288f;  // 1/sqrt(384)

    // Load Q tile once (= V rows, per the reference bug), scale folded in.
    {
        const float4* src = (const float4*)(Vb + (size_t)qt * 64 * H_DIM);
#pragma unroll
        for (int it = 0; it < 8; it++) {
            int f = it * 128 + tid;
            int n = f >> 4, c = f & 15;
            float4 v = src[f];
            v.x *= scale; v.y *= scale; v.z *= scale; v.w *= scale;
            *(float4*)&Qs[n * SQ + 4 * c] = v;
        }
    }

    float o[8][4];
    float mrow[8], lrow[8];
#pragma unroll
    for (int i = 0; i < 8; i++) {
        mrow[i] = -1e30f; lrow[i] = 0.f;
        o[i][0] = o[i][1] = o[i][2] = o[i][3] = 0.f;
    }

    for (int kt = 0; kt <= qt; kt++) {
        __syncthreads();   // previous PV done reading Vs/Ps

        // Cooperative K/V tile load (each 1024 float4s)
        {
            const float4* ksrc = (const float4*)(Kb + (size_t)kt * 64 * H_DIM);
            const float4* vsrc = (const float4*)(Vb + (size_t)kt * 64 * H_DIM);
#pragma unroll
            for (int it = 0; it < 8; it++) {
                int f = it * 128 + tid;
                int n = f >> 4, c = f & 15;
                *(float4*)&Ks[n * SK + 4 * c] = ksrc[f];
                *(float4*)&Vs[n * SV + 4 * c] = vsrc[f];
            }
        }
        __syncthreads();   // tiles (and Qs on first iter) visible

        // ---- S = Q . K^T  (8m x 4n per thread) ----
        float s[8][4];
#pragma unroll
        for (int i = 0; i < 8; i++)
            s[i][0] = s[i][1] = s[i][2] = s[i][3] = 0.f;

#pragma unroll
        for (int d0 = 0; d0 < H_DIM; d0 += 4) {
            float4 kf[4];
#pragma unroll
            for (int j = 0; j < 4; j++)
                kf[j] = *(const float4*)&Ks[(tx + 16 * j) * SK + d0];
#pragma unroll
            for (int i = 0; i < 8; i++) {
                float4 qf = *(const float4*)&Qs[(ty * 8 + i) * SQ + d0];
#pragma unroll
                for (int j = 0; j < 4; j++) {
                    s[i][j] += qf.x * kf[j].x;
                    s[i][j] += qf.y * kf[j].y;
                    s[i][j] += qf.z * kf[j].z;
                    s[i][j] += qf.w * kf[j].w;
                }
            }
        }

        // ---- causal mask (diagonal tile only) ----
        if (kt == qt) {
#pragma unroll
            for (int i = 0; i < 8; i++)
#pragma unroll
                for (int j = 0; j < 4; j++)
                    if (tx + 16 * j > ty * 8 + i) s[i][j] = -1e30f;
        }

        // ---- online softmax + P staging ----
#pragma unroll
        for (int i = 0; i < 8; i++) {
            float t = fmaxf(fmaxf(s[i][0], s[i][1]), fmaxf(s[i][2], s[i][3]));
            t = fmaxf(t, __shfl_xor_sync(0xffffffffu, t, 1));
            t = fmaxf(t, __shfl_xor_sync(0xffffffffu, t, 2));
            t = fmaxf(t, __shfl_xor_sync(0xffffffffu, t, 4));
            t = fmaxf(t, __shfl_xor_sync(0xffffffffu, t, 8));
            const float mnew = fmaxf(mrow[i], t);
            const float corr = __expf(mrow[i] - mnew);
            mrow[i] = mnew;
            lrow[i] *= corr;
            o[i][0] *= corr; o[i][1] *= corr; o[i][2] *= corr; o[i][3] *= corr;

            float psum = 0.f;
#pragma unroll
            for (int j = 0; j < 4; j++) {
                float p = __expf(s[i][j] - mnew);
                s[i][j] = p;
                psum += p;
            }
            psum += __shfl_xor_sync(0xffffffffu, psum, 1);
            psum += __shfl_xor_sync(0xffffffffu, psum, 2);
            psum += __shfl_xor_sync(0xffffffffu, psum, 4);
            psum += __shfl_xor_sync(0xffffffffu, psum, 8);
            lrow[i] += psum;

#pragma unroll
            for (int j = 0; j < 4; j++)
                Ps[(ty * 8 + i) * SP + tx + 16 * j] = s[i][j];
        }
        __syncthreads();   // P visible to all

        // ---- O += P . V  (8m x 4h per thread, h = 4*tx) ----
#pragma unroll
        for (int n0 = 0; n0 < 64; n0 += 4) {
            float4 vf[4];
#pragma unroll
            for (int nn = 0; nn < 4; nn++)
                vf[nn] = *(const float4*)&Vs[(n0 + nn) * SV + 4 * tx];
#pragma unroll
            for (int i = 0; i < 8; i++) {
                float4 pf = *(const float4*)&Ps[(ty * 8 + i) * SP + n0];
                o[i][0] += pf.x * vf[0].x; o[i][1] += pf.x * vf[0].y;
                o[i][2] += pf.x * vf[0].z; o[i][3] += pf.x * vf[0].w;
                o[i][0] += pf.y * vf[1].x; o[i][1] += pf.y * vf[1].y;
                o[i][2] += pf.y * vf[1].z; o[i][3] += pf.y * vf[1].w;
                o[i][0] += pf.z * vf[2].x; o[i][1] += pf.z * vf[2].y;
                o[i][2] += pf.z * vf[2].z; o[i][3] += pf.z * vf[2].w;
                o[i][0] += pf.w * vf[3].x; o[i][1] += pf.w * vf[3].y;
                o[i][2] += pf.w * vf[3].z; o[i][3] += pf.w * vf[3].w;
            }
        }
    }

    // ---- epilogue: normalize, store (coalesced float4) ----
#pragma unroll
    for (int i = 0; i < 8; i++) {
        const int qi = qt * 64 + ty * 8 + i;
        const float inv = 1.f / lrow[i];
        float4 ov;
        ov.x = o[i][0] * inv; ov.y = o[i][1] * inv;
        ov.z = o[i][2] * inv; ov.w = o[i][3] * inv;
        *(float4*)(out + ((size_t)b * T_DIM + qi) * H_DIM + 4 * tx) = ov;
    }
}

// ---------------------------------------------------------------------------
// Launch. Inputs (metadata order): x, Wk, bk, Wq, bq, Wv, bv.
// Wq/bq intentionally unused (reference uses the value projection for q).
// ---------------------------------------------------------------------------
extern "C" void kernel_launch(void* const* d_in, const int* in_sizes, int n_in,
                              void* d_out, int out_size)
{
    (void)in_sizes; (void)n_in; (void)out_size;
    const float* x  = (const float*)d_in[0];
    const float* Wk = (const float*)d_in[1];
    const float* bk = (const float*)d_in[2];
    const float* Wv = (const float*)d_in[5];
    const float* bv = (const float*)d_in[6];
    float* out = (float*)d_out;

    cudaFuncSetAttribute(flash_kernel,
                         cudaFuncAttributeMaxDynamicSharedMemorySize,
                         FLASH_SMEM);

    proj_kernel<<<BT_TOTAL / 64, 256>>>(x, Wk, bk, Wv, bv);

    dim3 grid(T_DIM / 64, B_DIM);
    flash_kernel<<<grid, 128, FLASH_SMEM>>>(out);
}